// round 15
// baseline (speedup 1.0000x reference)
#include <cuda_runtime.h>
#include <cuda_fp16.h>
#include <math.h>
#include <stdint.h>

#define BATCH 8
#define SEQ   4096
#define HID   256
#define NF    6

// Precombined per-batch weights, TRANSPOSED to [b][n][h], fp16.
__device__ __half g_B[BATCH * HID * HID];   // 1 MB (L2-resident)

// ===========================================================================
// Helpers
// ===========================================================================
__device__ __forceinline__ uint32_t smem_u32(const void* p) {
    uint32_t a;
    asm("{ .reg .u64 t; cvta.to.shared.u64 t, %1; cvt.u32.u64 %0, t; }" : "=r"(a) : "l"(p));
    return a;
}
__device__ __forceinline__ void cp_async16(uint32_t dst, const void* src) {
    asm volatile("cp.async.ca.shared.global [%0], [%1], 16;" :: "r"(dst), "l"(src));
}
#define CP_COMMIT()  asm volatile("cp.async.commit_group;" ::: "memory")
#define CP_WAIT(n)   asm volatile("cp.async.wait_group %0;" :: "n"(n) : "memory")

__device__ __forceinline__ void ldmx4(uint32_t a, uint32_t r[4]) {
    asm volatile("ldmatrix.sync.aligned.m8n8.x4.shared.b16 {%0,%1,%2,%3}, [%4];"
                 : "=r"(r[0]), "=r"(r[1]), "=r"(r[2]), "=r"(r[3]) : "r"(a));
}
__device__ __forceinline__ void mma16816(float c[4], const uint32_t a[4], const uint32_t b[2]) {
    asm volatile(
        "mma.sync.aligned.m16n8k16.row.col.f32.f16.f16.f32 "
        "{%0,%1,%2,%3},{%4,%5,%6,%7},{%8,%9},{%0,%1,%2,%3};"
        : "+f"(c[0]), "+f"(c[1]), "+f"(c[2]), "+f"(c[3])
        : "r"(a[0]), "r"(a[1]), "r"(a[2]), "r"(a[3]), "r"(b[0]), "r"(b[1]));
}

// Swizzled byte offset inside a [rows][64 fp16] tile (128B rows, XOR swizzle)
__device__ __forceinline__ uint32_t sw_off(int r, int k) {
    int c = k >> 3;
    return (uint32_t)((r << 7) + ((c ^ (r & 7)) << 4) + ((k & 7) << 1));
}

// ===========================================================================
// Kernel 1: build combined weights, transposed, fp16. grid (32, 8), 256 thr.
//   g_B[b][n][h] = fp16( sum_f W[f][h][n] * sin(freq_f*t_b + phase[f][n]) )
// ===========================================================================
__global__ __launch_bounds__(256) void build_M_kernel(
    const float* __restrict__ W,      // [F, H, H]
    const float* __restrict__ phase,  // [F, H]
    const float* __restrict__ t)      // [B, 1]
{
    __shared__ __half s_hi[8][HID];

    const int b  = blockIdx.y;
    const int h0 = blockIdx.x * 8;
    const int k  = threadIdx.x;
    const float tb = t[b];
    const float freqs[NF] = {1.f, 2.f, 4.f, 8.f, 7.f, 5.f};
    float res[NF];
#pragma unroll
    for (int f = 0; f < NF; f++) res[f] = sinf(freqs[f] * tb + phase[f * HID + k]);

#pragma unroll
    for (int hl = 0; hl < 8; hl++) {
        float acc = 0.f;
#pragma unroll
        for (int f = 0; f < NF; f++)
            acc = fmaf(W[((size_t)f * HID + h0 + hl) * HID + k], res[f], acc);
        s_hi[hl][k] = __float2half_rn(acc);
    }
    __syncthreads();

    const int n = k;
    __half th[8];
#pragma unroll
    for (int j = 0; j < 8; j++) th[j] = s_hi[j][n];
    *(uint4*)&g_B[((size_t)b * HID + n) * HID + h0] = *(uint4*)th;
}

// ===========================================================================
// Kernel 2: fp16 mma.sync GEMM — R7 structure (best verified) + L1 diet.
// CTA tile 128 x 128, 256 threads, 2 CTAs/SM, grid (2, 32, 8).
// A (128x256) converted fp32->fp16 ONCE into resident smem (64 KB, STS.128).
// B streamed in 4 k-chunks (16 KB/stage, double-buffered cp.async).
// ===========================================================================
#define OFF_A      0                  // 4 chunk-tiles x 16 KB = 64 KB
#define OFF_B      65536              // 2 stages x 16 KB
#define SMEM_TOTAL (65536 + 32768)    // 96 KB

__global__ __launch_bounds__(256, 2) void gemm_kernel(
    const float* __restrict__ X,   // [B, SEQ, HID]
    float* __restrict__ Y)         // [B, SEQ, HID]
{
    extern __shared__ char smem[];
    const uint32_t sb = smem_u32(smem);
    const int tid  = threadIdx.x;
    const int wid  = tid >> 5;
    const int lane = tid & 31;
    const int b    = blockIdx.z;
    const int row0 = blockIdx.y * 128;
    const int col0 = blockIdx.x * 128;

    // 8 warps: 2 (m) x 4 (n); warp tile 64 rows x 32 cols
    const int wm = (wid & 1) * 64;
    const int wn = (wid >> 1) * 32;

    const float*  A32 = X   + ((size_t)b * SEQ + row0) * HID;
    const __half* Bg  = g_B + ((size_t)b * HID + col0) * HID;

    float acc[4][4][4];
#pragma unroll
    for (int i = 0; i < 4; i++)
#pragma unroll
        for (int j = 0; j < 4; j++)
#pragma unroll
            for (int q = 0; q < 4; q++) acc[i][j][q] = 0.f;

    // B loader: 128 n-rows x 64 k halves; 256 thr -> 4 cp.async each
    const int lr = tid >> 3;   // 0..31 (+32i)
    const int lc = tid & 7;    // 16B chunk

#define LOAD_B(stage, kk)                                                       \
    do {                                                                        \
        _Pragma("unroll")                                                       \
        for (int i = 0; i < 4; i++) {                                           \
            int r = lr + i * 32;                                                \
            uint32_t o = (uint32_t)((stage) * 16384) + sw_off(r, 0) +           \
                         (uint32_t)(((lc ^ (r & 7)) ^ (r & 7)) * 0);            \
            (void)o;                                                            \
            cp_async16(sb + OFF_B + (uint32_t)((stage) * 16384) +               \
                       (uint32_t)((r << 7) + ((lc ^ (r & 7)) << 4)),            \
                       &Bg[(size_t)r * HID + (kk) + lc * 8]);                   \
        }                                                                       \
        CP_COMMIT();                                                            \
    } while (0)

    // ---- prologue: start B chunk 0, then convert whole A panel (x read once)
    LOAD_B(0, 0);
    {
        const int row = tid >> 1;             // 0..127
        const int kh  = (tid & 1) * 128;      // k region of 128 floats
#pragma unroll
        for (int i = 0; i < 8; i++) {
            const int k = kh + i * 16;        // 16 contiguous floats
            const float* ap = A32 + (size_t)row * HID + k;
            float4 v[4];
#pragma unroll
            for (int q = 0; q < 4; q++) v[q] = *(const float4*)&ap[q * 4];
            uint4 p0, p1;
            __half2 h;
            h = __floats2half2_rn(v[0].x, v[0].y); p0.x = *(uint32_t*)&h;
            h = __floats2half2_rn(v[0].z, v[0].w); p0.y = *(uint32_t*)&h;
            h = __floats2half2_rn(v[1].x, v[1].y); p0.z = *(uint32_t*)&h;
            h = __floats2half2_rn(v[1].z, v[1].w); p0.w = *(uint32_t*)&h;
            h = __floats2half2_rn(v[2].x, v[2].y); p1.x = *(uint32_t*)&h;
            h = __floats2half2_rn(v[2].z, v[2].w); p1.y = *(uint32_t*)&h;
            h = __floats2half2_rn(v[3].x, v[3].y); p1.z = *(uint32_t*)&h;
            h = __floats2half2_rn(v[3].z, v[3].w); p1.w = *(uint32_t*)&h;
            const uint32_t base = (uint32_t)(k >> 6) * 16384;
            *(uint4*)(smem + OFF_A + base + sw_off(row, k & 63))       = p0;
            *(uint4*)(smem + OFF_A + base + sw_off(row, (k & 63) + 8)) = p1;
        }
    }

    // Fragment addressing constants
    const int arow = wm + (lane & 15);
    const int akof = (lane >> 4) << 3;
    const int bm   = lane >> 3;
    const int brq  = ((bm >> 1) << 3) + (lane & 7);
    const int bkof = (bm & 1) << 3;

#pragma unroll
    for (int c = 0; c < 4; c++) {
        if (c + 1 < 4) LOAD_B((c + 1) & 1, (c + 1) * 64);
        if (c < 3) CP_WAIT(1); else CP_WAIT(0);
        __syncthreads();

        const uint32_t aoff = sb + OFF_A + (uint32_t)c * 16384;
        const uint32_t boff = sb + OFF_B + (uint32_t)(c & 1) * 16384;

#pragma unroll
        for (int s = 0; s < 4; s++) {
            uint32_t ah[4][4], bb[2][4];
            const int akk = s * 16 + akof;
#pragma unroll
            for (int mi = 0; mi < 4; mi++)
                ldmx4(aoff + sw_off(arow + mi * 16, akk), ah[mi]);
            const int bkq = s * 16 + bkof;
#pragma unroll
            for (int p = 0; p < 2; p++)
                ldmx4(boff + sw_off(wn + p * 16 + brq, bkq), bb[p]);
#pragma unroll
            for (int mi = 0; mi < 4; mi++)
#pragma unroll
                for (int p = 0; p < 2; p++) {
                    mma16816(acc[mi][p * 2 + 0], ah[mi], &bb[p][0]);
                    mma16816(acc[mi][p * 2 + 1], ah[mi], &bb[p][2]);
                }
        }
        __syncthreads();
    }

    // ---- epilogue: streaming stores (output never re-read)
    float* C = Y + ((size_t)b * SEQ + row0) * HID + col0;
#pragma unroll
    for (int mi = 0; mi < 4; mi++) {
        int r0 = wm + mi * 16 + (lane >> 2);
#pragma unroll
        for (int nj = 0; nj < 4; nj++) {
            int cc = wn + nj * 8 + (lane & 3) * 2;
            __stcs((float2*)&C[(size_t)r0 * HID + cc],
                   make_float2(acc[mi][nj][0], acc[mi][nj][1]));
            __stcs((float2*)&C[(size_t)(r0 + 8) * HID + cc],
                   make_float2(acc[mi][nj][2], acc[mi][nj][3]));
        }
    }
#undef LOAD_B
}

// ===========================================================================
extern "C" void kernel_launch(void* const* d_in, const int* in_sizes, int n_in,
                              void* d_out, int out_size) {
    const float* x     = (const float*)d_in[0];  // [8, 4096, 256]
    const float* t     = (const float*)d_in[1];  // [8, 1]
    const float* osc   = (const float*)d_in[2];  // [6, 256, 256]
    const float* phase = (const float*)d_in[3];  // [6, 256]
    float* out = (float*)d_out;                  // [8, 4096, 256]
    (void)in_sizes; (void)n_in; (void)out_size;

    cudaFuncSetAttribute(gemm_kernel, cudaFuncAttributeMaxDynamicSharedMemorySize, SMEM_TOTAL);

    build_M_kernel<<<dim3(32, BATCH), 256>>>(osc, phase, t);
    gemm_kernel<<<dim3(2, 32, BATCH), 256, SMEM_TOTAL>>>(x, out);
}

// round 16
// speedup vs baseline: 1.2674x; 1.2674x over previous
#include <cuda_runtime.h>
#include <cuda_fp16.h>
#include <math.h>
#include <stdint.h>

#define BATCH 8
#define SEQ   4096
#define HID   256
#define NF    6

// Precombined per-batch weights, TRANSPOSED to [b][n][h], fp16.
__device__ __half g_B[BATCH * HID * HID];   // 1 MB (L2-resident)

// ===========================================================================
// Helpers
// ===========================================================================
__device__ __forceinline__ uint32_t smem_u32(const void* p) {
    uint32_t a;
    asm("{ .reg .u64 t; cvta.to.shared.u64 t, %1; cvt.u32.u64 %0, t; }" : "=r"(a) : "l"(p));
    return a;
}
__device__ __forceinline__ void cp_async16(uint32_t dst, const void* src) {
    asm volatile("cp.async.ca.shared.global [%0], [%1], 16;" :: "r"(dst), "l"(src));
}
#define CP_COMMIT()  asm volatile("cp.async.commit_group;" ::: "memory")
#define CP_WAIT(n)   asm volatile("cp.async.wait_group %0;" :: "n"(n) : "memory")

__device__ __forceinline__ void ldmx4(uint32_t a, uint32_t r[4]) {
    asm volatile("ldmatrix.sync.aligned.m8n8.x4.shared.b16 {%0,%1,%2,%3}, [%4];"
                 : "=r"(r[0]), "=r"(r[1]), "=r"(r[2]), "=r"(r[3]) : "r"(a));
}
__device__ __forceinline__ void mma16816(float c[4], const uint32_t a[4], const uint32_t b[2]) {
    asm volatile(
        "mma.sync.aligned.m16n8k16.row.col.f32.f16.f16.f32 "
        "{%0,%1,%2,%3},{%4,%5,%6,%7},{%8,%9},{%0,%1,%2,%3};"
        : "+f"(c[0]), "+f"(c[1]), "+f"(c[2]), "+f"(c[3])
        : "r"(a[0]), "r"(a[1]), "r"(a[2]), "r"(a[3]), "r"(b[0]), "r"(b[1]));
}

// Swizzled byte offset inside a [rows][64 fp16] tile (128B rows, XOR swizzle)
__device__ __forceinline__ uint32_t sw_off(int r, int k) {
    int c = k >> 3;
    return (uint32_t)((r << 7) + ((c ^ (r & 7)) << 4) + ((k & 7) << 1));
}

// ===========================================================================
// Kernel 1: build combined weights, transposed, fp16. grid (32, 8), 256 thr.
//   g_B[b][n][h] = fp16( sum_f W[f][h][n] * sin(freq_f*t_b + phase[f][n]) )
// ===========================================================================
__global__ __launch_bounds__(256) void build_M_kernel(
    const float* __restrict__ W,      // [F, H, H]
    const float* __restrict__ phase,  // [F, H]
    const float* __restrict__ t)      // [B, 1]
{
    __shared__ __half s_hi[8][HID];

    const int b  = blockIdx.y;
    const int h0 = blockIdx.x * 8;
    const int k  = threadIdx.x;
    const float tb = t[b];
    const float freqs[NF] = {1.f, 2.f, 4.f, 8.f, 7.f, 5.f};
    float res[NF];
#pragma unroll
    for (int f = 0; f < NF; f++) res[f] = sinf(freqs[f] * tb + phase[f * HID + k]);

#pragma unroll
    for (int hl = 0; hl < 8; hl++) {
        float acc = 0.f;
#pragma unroll
        for (int f = 0; f < NF; f++)
            acc = fmaf(W[((size_t)f * HID + h0 + hl) * HID + k], res[f], acc);
        s_hi[hl][k] = __float2half_rn(acc);
    }
    __syncthreads();

    const int n = k;
    __half th[8];
#pragma unroll
    for (int j = 0; j < 8; j++) th[j] = s_hi[j][n];
    *(uint4*)&g_B[((size_t)b * HID + n) * HID + h0] = *(uint4*)th;
}

// ===========================================================================
// Kernel 2: fused fp16 mma.sync GEMM (R10 structure).
// CTA = 128 rows x FULL 256 cols in two 128-col strips over smem-resident A
// (x read ONCE; batched-MLP convert prologue). B: 8 chunks, 2x16 KB cp.async
// ring, chunks 0+1 in flight during the convert. 256 thr, 2 CTAs/SM.
// ===========================================================================
#define OFF_A      0                   // 4 chunk-tiles x 16 KB
#define OFF_B      65536               // 2 stages x 16 KB
#define SMEM_TOTAL (65536 + 32768)     // 96 KB

__global__ __launch_bounds__(256, 2) void gemm_kernel(
    const float* __restrict__ X,   // [B, SEQ, HID]
    float* __restrict__ Y)         // [B, SEQ, HID]
{
    extern __shared__ char smem[];
    const uint32_t sb = smem_u32(smem);
    const int tid  = threadIdx.x;
    const int wid  = tid >> 5;
    const int lane = tid & 31;
    const int b    = blockIdx.y;
    const int row0 = blockIdx.x * 128;

    // 8 warps: 2 (m) x 4 (n); warp tile 64 rows x 32 cols within a strip
    const int wm = (wid & 1) * 64;
    const int wn = (wid >> 1) * 32;

    const float*  A32 = X   + ((size_t)b * SEQ + row0) * HID;
    const __half* Bg  = g_B + (size_t)b * HID * HID;
    float*        C   = Y   + ((size_t)b * SEQ + row0) * HID;

    // B loader: chunk j -> col strip (j>>2)*128, k (j&3)*64; stage j&1
    const int blr = tid >> 3, blc = tid & 7;
#define ISSUE_B(j)                                                              \
    do {                                                                        \
        const uint32_t st = sb + OFF_B + (uint32_t)((j) & 1) * 16384;           \
        const __half* bp = Bg + (size_t)(((j) >> 2) * 128) * HID + ((j) & 3) * 64; \
        _Pragma("unroll")                                                       \
        for (int i = 0; i < 4; i++) {                                           \
            int r = blr + i * 32;                                               \
            cp_async16(st + sw_off(r, blc * 8), &bp[(size_t)r * HID + blc * 8]); \
        }                                                                       \
        CP_COMMIT();                                                            \
    } while (0)

#define COMPUTE(j)                                                              \
    do {                                                                        \
        const uint32_t aoff = sb + OFF_A + (uint32_t)((j) & 3) * 16384;         \
        const uint32_t boff = sb + OFF_B + (uint32_t)((j) & 1) * 16384;         \
        _Pragma("unroll")                                                       \
        for (int s = 0; s < 4; s++) {                                           \
            uint32_t ah[4][4], bb[2][4];                                        \
            const int arow = wm + (lane & 15);                                  \
            const int akk  = s * 16 + ((lane >> 4) << 3);                       \
            _Pragma("unroll")                                                   \
            for (int mi = 0; mi < 4; mi++)                                      \
                ldmx4(aoff + sw_off(arow + mi * 16, akk), ah[mi]);              \
            const int bm  = lane >> 3;                                          \
            const int brq = ((bm >> 1) << 3) + (lane & 7);                      \
            const int bkq = s * 16 + ((bm & 1) << 3);                           \
            _Pragma("unroll")                                                   \
            for (int p = 0; p < 2; p++)                                         \
                ldmx4(boff + sw_off(wn + p * 16 + brq, bkq), bb[p]);            \
            _Pragma("unroll")                                                   \
            for (int mi = 0; mi < 4; mi++)                                      \
                _Pragma("unroll")                                               \
                for (int p = 0; p < 2; p++) {                                   \
                    mma16816(acc[mi][p * 2 + 0], ah[mi], &bb[p][0]);            \
                    mma16816(acc[mi][p * 2 + 1], ah[mi], &bb[p][2]);            \
                }                                                               \
        }                                                                       \
    } while (0)

#define EPILOGUE(strip)                                                         \
    do {                                                                        \
        float* Ct = C + (strip) * 128;                                          \
        _Pragma("unroll")                                                       \
        for (int mi = 0; mi < 4; mi++) {                                        \
            int r0 = wm + mi * 16 + (lane >> 2);                                \
            _Pragma("unroll")                                                   \
            for (int nj = 0; nj < 4; nj++) {                                    \
                int cc = wn + nj * 8 + (lane & 3) * 2;                          \
                *(float2*)&Ct[(size_t)r0 * HID + cc] =                          \
                    make_float2(acc[mi][nj][0], acc[mi][nj][1]);                \
                *(float2*)&Ct[(size_t)(r0 + 8) * HID + cc] =                    \
                    make_float2(acc[mi][nj][2], acc[mi][nj][3]);                \
                acc[mi][nj][0] = acc[mi][nj][1] = 0.f;                          \
                acc[mi][nj][2] = acc[mi][nj][3] = 0.f;                          \
            }                                                                   \
        }                                                                       \
    } while (0)

    // ---- prologue: B chunks 0 AND 1 in flight, then convert whole A panel
    // (x read once; 2 rounds of 16 batched LDG.128 for MLP)
    ISSUE_B(0);
    ISSUE_B(1);
    {
        const int row = tid >> 1;
        const int kq  = (tid & 1) * 32;
#pragma unroll
        for (int half = 0; half < 2; half++) {
            const float* ap = A32 + (size_t)row * HID + half * 128 + kq;
            float4 v[16];
#pragma unroll
            for (int i = 0; i < 16; i++)
                v[i] = *(const float4*)&ap[(i >> 3) * 64 + (i & 7) * 4];
#pragma unroll
            for (int i = 0; i < 16; i++) {
                __half2 h01 = __floats2half2_rn(v[i].x, v[i].y);
                __half2 h23 = __floats2half2_rn(v[i].z, v[i].w);
                uint2 p; p.x = *(uint32_t*)&h01; p.y = *(uint32_t*)&h23;
                *(uint2*)(smem + OFF_A + (half * 2 + (i >> 3)) * 16384 +
                          sw_off(row, kq + (i & 7) * 4)) = p;
            }
        }
    }

    float acc[4][4][4];
#pragma unroll
    for (int i = 0; i < 4; i++)
#pragma unroll
        for (int j = 0; j < 4; j++)
#pragma unroll
            for (int q = 0; q < 4; q++) acc[i][j][q] = 0.f;

    // ---- 8-chunk pipeline (2-stage ring, chunks 0/1 pre-issued):
    //   iter j>=1 issues j+1 into the stage consumed at j-1 (barriered),
    //   waits for chunk j, computes j. Two syncs per chunk (R10-proven).
#pragma unroll
    for (int j = 0; j < 8; j++) {
        if (j >= 1 && j + 1 < 8) ISSUE_B(j + 1);
        if (j < 7) CP_WAIT(1); else CP_WAIT(0);
        __syncthreads();
        COMPUTE(j);
        if (j == 3) EPILOGUE(0);
        __syncthreads();
    }
    EPILOGUE(1);

#undef ISSUE_B
#undef COMPUTE
#undef EPILOGUE
}

// ===========================================================================
extern "C" void kernel_launch(void* const* d_in, const int* in_sizes, int n_in,
                              void* d_out, int out_size) {
    const float* x     = (const float*)d_in[0];  // [8, 4096, 256]
    const float* t     = (const float*)d_in[1];  // [8, 1]
    const float* osc   = (const float*)d_in[2];  // [6, 256, 256]
    const float* phase = (const float*)d_in[3];  // [6, 256]
    float* out = (float*)d_out;                  // [8, 4096, 256]
    (void)in_sizes; (void)n_in; (void)out_size;

    cudaFuncSetAttribute(gemm_kernel, cudaFuncAttributeMaxDynamicSharedMemorySize, SMEM_TOTAL);

    build_M_kernel<<<dim3(32, BATCH), 256>>>(osc, phase, t);
    gemm_kernel<<<dim3(SEQ / 128, BATCH), 256, SMEM_TOTAL>>>(x, out);
}